// round 12
// baseline (speedup 1.0000x reference)
#include <cuda_runtime.h>
#include <cuda_fp16.h>

#define BATCH 128
#define NTF 1024
#define NGENES 20000
#define NPAIRS (NGENES / 2)      // 10000 gene-pairs
#define NEDGE1 (NGENES * 64)     // 1,280,000 layer-1 edges
#define NEDGE_HALF (NEDGE1 / 2)
#define CHUNK 64                 // batch elements per block
#define THREADS 1024             // 32 warps
#define GRID 148                 // one wave, 74 blocks per chunk
#define SMEM_BYTES (NTF * CHUNK * 2)  // 131072
#define TICK_PAIRS 4
#define NTICKETS (NPAIRS / TICK_PAIRS)   // 2500 per chunk, exact

// device scratch
__device__ __half g_xTh[NTF * BATCH];        // transposed fp16 features
__device__ unsigned short g_i16[NEDGE1];     // u16 edge indices
__device__ __half g_w1h[NEDGE1];             // fp16 layer-1 weights
__device__ uint4  g_tail[NGENES * 4];        // 64B/gene packed tail
__device__ __half g_yTh[NGENES * BATCH];     // gene-major fp16 output
__device__ unsigned int g_ticket[2];

__device__ __forceinline__ unsigned int packh2(float a, float b) {
    const __half2 h = __float22half2_rn(make_float2(a, b));
    return *reinterpret_cast<const unsigned int*>(&h);
}
__device__ __forceinline__ unsigned int pack16(int a, int b) {
    return (unsigned int)a | ((unsigned int)b << 16);
}

// ---- prep A/B: edge tables, 16 edges/thread, half the table per launch ----
__global__ void prep_edges(const int* __restrict__ in1,
                           const float* __restrict__ w1, int base) {
    const int e = base + (blockIdx.x * 256 + threadIdx.x) * 16;
    if (e + 16 <= base + NEDGE_HALF) {
        const int4 i0 = __ldg((const int4*)(in1 + e));
        const int4 i1 = __ldg((const int4*)(in1 + e) + 1);
        const int4 i2 = __ldg((const int4*)(in1 + e) + 2);
        const int4 i3 = __ldg((const int4*)(in1 + e) + 3);
        const float4 a0 = __ldg((const float4*)(w1 + e));
        const float4 a1 = __ldg((const float4*)(w1 + e) + 1);
        const float4 a2 = __ldg((const float4*)(w1 + e) + 2);
        const float4 a3 = __ldg((const float4*)(w1 + e) + 3);
        uint4 ia, ib, wa, wb;
        ia.x = pack16(i0.x, i0.y); ia.y = pack16(i0.z, i0.w);
        ia.z = pack16(i1.x, i1.y); ia.w = pack16(i1.z, i1.w);
        ib.x = pack16(i2.x, i2.y); ib.y = pack16(i2.z, i2.w);
        ib.z = pack16(i3.x, i3.y); ib.w = pack16(i3.z, i3.w);
        wa.x = packh2(a0.x, a0.y); wa.y = packh2(a0.z, a0.w);
        wa.z = packh2(a1.x, a1.y); wa.w = packh2(a1.z, a1.w);
        wb.x = packh2(a2.x, a2.y); wb.y = packh2(a2.z, a2.w);
        wb.z = packh2(a3.x, a3.y); wb.w = packh2(a3.z, a3.w);
        *(uint4*)(g_i16 + e) = ia;
        *(uint4*)(g_i16 + e + 8) = ib;
        *(uint4*)(g_w1h + e) = wa;
        *(uint4*)(g_w1h + e + 8) = wb;
    }
}

// ---- prep C: feature transpose + tail structs + ticket reset ----
__global__ void prep_feat(const float* __restrict__ f,
                          const float* __restrict__ w2,
                          const float* __restrict__ b1,
                          const float* __restrict__ b2,
                          const float* __restrict__ w3,
                          const float* __restrict__ b3) {
    const int bid = blockIdx.x;
    if (bid < 128) {
        __shared__ float tile[32][33];
        const int tx = threadIdx.x & 31, ty = threadIdx.x >> 5;
        const int t0 = (bid & 31) * 32;   // TF base
        const int b0 = (bid >> 5) * 32;   // batch base
#pragma unroll
        for (int j = 0; j < 32; j += 8)
            tile[ty + j][tx] = f[(b0 + ty + j) * NTF + t0 + tx];
        __syncthreads();
#pragma unroll
        for (int j = 0; j < 32; j += 8)
            g_xTh[(t0 + ty + j) * BATCH + b0 + tx] = __float2half(tile[tx][ty + j]);
        if (bid == 0 && threadIdx.x < 2) g_ticket[threadIdx.x] = 0u;
    } else {
        const int g = (bid - 128) * 256 + threadIdx.x;
        if (g < NGENES) {
            const float4 q0 = __ldg((const float4*)(w2 + g * 16));
            const float4 q1 = __ldg((const float4*)(w2 + g * 16) + 1);
            const float4 q2 = __ldg((const float4*)(w2 + g * 16) + 2);
            const float4 q3 = __ldg((const float4*)(w2 + g * 16) + 3);
            const float4 b1q = __ldg((const float4*)(b1 + g * 4));
            const float4 b2q = __ldg((const float4*)(b2 + g * 4));
            const float4 w3q = __ldg((const float4*)(w3 + g * 4));
            const float  b3s = __ldg(b3 + g);
            uint4 u0, u1, u2, u3;
            u0.x = packh2(q0.x, q0.y); u0.y = packh2(q0.z, q0.w);
            u0.z = packh2(q1.x, q1.y); u0.w = packh2(q1.z, q1.w);
            u1.x = packh2(q2.x, q2.y); u1.y = packh2(q2.z, q2.w);
            u1.z = packh2(q3.x, q3.y); u1.w = packh2(q3.z, q3.w);
            u2.x = packh2(b1q.x, b1q.y); u2.y = packh2(b1q.z, b1q.w);
            u2.z = packh2(b2q.x, b2q.y); u2.w = packh2(b2q.z, b2q.w);
            u3.x = packh2(w3q.x, w3q.y); u3.y = packh2(w3q.z, w3q.w);
            u3.z = packh2(b3s, b3s);     u3.w = 0u;
            uint4* dst = g_tail + (size_t)g * 4;
            dst[0] = u0; dst[1] = u1; dst[2] = u2; dst[3] = u3;
        }
    }
}

// g_yTh [NGENES][BATCH] fp16 -> out [BATCH][NGENES] fp32
__global__ void transpose_out(float* __restrict__ out) {
    __shared__ float tile[32][33];
    const int tx = threadIdx.x, ty = threadIdx.y;
    const int g0 = blockIdx.x * 32;
    const int b0 = blockIdx.y * 32;
#pragma unroll
    for (int j = 0; j < 32; j += 8)
        tile[ty + j][tx] = __half2float(g_yTh[(size_t)(g0 + ty + j) * BATCH + b0 + tx]);
    __syncthreads();
#pragma unroll
    for (int j = 0; j < 32; j += 8)
        out[(size_t)(b0 + ty + j) * NGENES + g0 + tx] = tile[tx][ty + j];
}

__device__ __forceinline__ __half2 u2h(unsigned int u) {
    return *reinterpret_cast<__half2*>(&u);
}
__device__ __forceinline__ __half2 tanh_h2f(float2 a) {
    __half2 h = __float22half2_rn(a);
    unsigned int u = *reinterpret_cast<unsigned int*>(&h), r;
    asm("tanh.approx.f16x2 %0, %1;" : "=r"(r) : "r"(u));
    return u2h(r);
}
__device__ __forceinline__ __half2 tanh_h2(__half2 s) {
    unsigned int u = *reinterpret_cast<unsigned int*>(&s), r;
    asm("tanh.approx.f16x2 %0, %1;" : "=r"(r) : "r"(u));
    return u2h(r);
}

// 4 edges (2 packed index words), LDS.64 row gathers, fp16 chain, fp32 acc
__device__ __forceinline__ void edge_group(const char* fb, unsigned int e01,
                                           unsigned int e23, unsigned int wlo,
                                           unsigned int whi, float4& acc) {
    const uint2 x0 = *(const uint2*)(fb + ((e01 & 0xFFFFu) << 7));
    const uint2 x1 = *(const uint2*)(fb + ((e01 >> 16) << 7));
    const uint2 x2 = *(const uint2*)(fb + ((e23 & 0xFFFFu) << 7));
    const uint2 x3 = *(const uint2*)(fb + ((e23 >> 16) << 7));
    __half2 alo = __hmul2(__low2half2(u2h(wlo)),  u2h(x0.x));
    __half2 ahi = __hmul2(__low2half2(u2h(wlo)),  u2h(x0.y));
    alo = __hfma2(__high2half2(u2h(wlo)), u2h(x1.x), alo);
    ahi = __hfma2(__high2half2(u2h(wlo)), u2h(x1.y), ahi);
    alo = __hfma2(__low2half2(u2h(whi)),  u2h(x2.x), alo);
    ahi = __hfma2(__low2half2(u2h(whi)),  u2h(x2.y), ahi);
    alo = __hfma2(__high2half2(u2h(whi)), u2h(x3.x), alo);
    ahi = __hfma2(__high2half2(u2h(whi)), u2h(x3.y), ahi);
    const float2 flo = __half22float2(alo);
    const float2 fhi = __half22float2(ahi);
    acc.x += flo.x; acc.y += flo.y; acc.z += fhi.x; acc.w += fhi.y;
}

// layer-1 node: 16 edges, two independent fp32 accumulators
__device__ __forceinline__ void l1_node(const char* fb, uint4 ia, uint4 ib,
                                        uint4 wa, uint4 wb, float bias,
                                        __half2& hlo, __half2& hhi) {
    float4 a0 = make_float4(bias, bias, bias, bias);
    float4 a1 = make_float4(0.f, 0.f, 0.f, 0.f);
    edge_group(fb, ia.x, ia.y, wa.x, wa.y, a0);
    edge_group(fb, ia.z, ia.w, wa.z, wa.w, a1);
    edge_group(fb, ib.x, ib.y, wb.x, wb.y, a0);
    edge_group(fb, ib.z, ib.w, wb.z, wb.w, a1);
    hlo = tanh_h2f(make_float2(a0.x + a1.x, a0.y + a1.y));
    hhi = tanh_h2f(make_float2(a0.z + a1.z, a0.w + a1.w));
}

// layer-2 node + layer-3 accumulate, all fp16 (12 inst)
__device__ __forceinline__ void l23_node(const __half2* h1lo, const __half2* h1hi,
                                         unsigned int wlo, unsigned int whi,
                                         __half2 b2h, __half2 w3h,
                                         __half2& ylo, __half2& yhi) {
    __half2 slo = b2h, shi = b2h;
    slo = __hfma2(__low2half2(u2h(wlo)),  h1lo[0], slo);
    shi = __hfma2(__low2half2(u2h(wlo)),  h1hi[0], shi);
    slo = __hfma2(__high2half2(u2h(wlo)), h1lo[1], slo);
    shi = __hfma2(__high2half2(u2h(wlo)), h1hi[1], shi);
    slo = __hfma2(__low2half2(u2h(whi)),  h1lo[2], slo);
    shi = __hfma2(__low2half2(u2h(whi)),  h1hi[2], shi);
    slo = __hfma2(__high2half2(u2h(whi)), h1lo[3], slo);
    shi = __hfma2(__high2half2(u2h(whi)), h1hi[3], shi);
    ylo = __hfma2(w3h, tanh_h2(slo), ylo);
    yhi = __hfma2(w3h, tanh_h2(shi), yhi);
}

__global__ void __launch_bounds__(THREADS, 1) fused_kernel() {
    extern __shared__ unsigned int xs[];   // [NTF][32] uint -> 128B fp16 rows
    const int tid = threadIdx.x;
    const int chunk = blockIdx.x & 1;      // 148 blocks -> 74 per chunk
    const int b0 = chunk * CHUNK;

    // fill feature slice (rows of 64 fp16 = 8 uint4)
    {
        const uint4* src = (const uint4*)g_xTh;  // global row = 16 uint4
        uint4* dst = (uint4*)xs;
#pragma unroll
        for (int i = tid; i < NTF * 8; i += THREADS) {
            const int t = i >> 3, c = i & 7;
            dst[i] = src[t * 16 + chunk * 8 + c];
        }
    }
    __syncthreads();

    const int lane = tid & 31;
    const int gl   = lane >> 4;     // gene within pair (0..1)
    const int bsub = lane & 15;     // batch quad -> batches b0+bsub*4 .. +3
    const char* fb = (const char*)xs + bsub * 8;   // lane's 4-batch column
    unsigned int* cnt = &g_ticket[chunk];

    // ticketed work stealing, 4 pairs per ticket, prefetched
    int t = 0;
    if (lane == 0) t = (int)atomicAdd(cnt, 1u);
    t = __shfl_sync(0xffffffffu, t, 0);

    while (t < NTICKETS) {
        int tn = 0;
        if (lane == 0) tn = (int)atomicAdd(cnt, 1u);
        tn = __shfl_sync(0xffffffffu, tn, 0);

        const int pbase = t * TICK_PAIRS;
#pragma unroll 1
        for (int k = 0; k < TICK_PAIRS; k++) {
            const int g = (pbase + k) * 2 + gl;
            const uint4* ip = (const uint4*)(g_i16 + (size_t)g * 64);
            const uint4* wp = (const uint4*)(g_w1h + (size_t)g * 64);
            const uint4* tp = g_tail + (size_t)g * 4;

            const uint4 u2 = __ldg(tp + 2);   // b1h x4, b2h x4
            const uint4 u3 = __ldg(tp + 3);   // w3h x4, b3h2
            const float2 b1a = __half22float2(u2h(u2.x));
            const float2 b1b = __half22float2(u2h(u2.y));

            __half2 h1lo[4], h1hi[4];
            l1_node(fb, __ldg(ip + 0), __ldg(ip + 1), __ldg(wp + 0), __ldg(wp + 1),
                    b1a.x, h1lo[0], h1hi[0]);
            l1_node(fb, __ldg(ip + 2), __ldg(ip + 3), __ldg(wp + 2), __ldg(wp + 3),
                    b1a.y, h1lo[1], h1hi[1]);
            // w2 loads issued mid-layer-1: latency drains under nodes 2-3
            const uint4 u0 = __ldg(tp + 0);
            const uint4 u1 = __ldg(tp + 1);
            l1_node(fb, __ldg(ip + 4), __ldg(ip + 5), __ldg(wp + 4), __ldg(wp + 5),
                    b1b.x, h1lo[2], h1hi[2]);
            l1_node(fb, __ldg(ip + 6), __ldg(ip + 7), __ldg(wp + 6), __ldg(wp + 7),
                    b1b.y, h1lo[3], h1hi[3]);

            // layers 2+3, all fp16
            const __half2 b3h = u2h(u3.z);
            __half2 ylo = b3h, yhi = b3h;
            l23_node(h1lo, h1hi, u0.x, u0.y,
                     __low2half2(u2h(u2.z)),  __low2half2(u2h(u3.x)),  ylo, yhi);
            l23_node(h1lo, h1hi, u0.z, u0.w,
                     __high2half2(u2h(u2.z)), __high2half2(u2h(u3.x)), ylo, yhi);
            l23_node(h1lo, h1hi, u1.x, u1.y,
                     __low2half2(u2h(u2.w)),  __low2half2(u2h(u3.y)),  ylo, yhi);
            l23_node(h1lo, h1hi, u1.z, u1.w,
                     __high2half2(u2h(u2.w)), __high2half2(u2h(u3.y)), ylo, yhi);

            uint2 yy;
            yy.x = *reinterpret_cast<const unsigned int*>(&ylo);
            yy.y = *reinterpret_cast<const unsigned int*>(&yhi);
            *(uint2*)&g_yTh[(size_t)g * BATCH + b0 + bsub * 4] = yy;
        }
        t = tn;
    }
}

extern "C" void kernel_launch(void* const* d_in, const int* in_sizes, int n_in,
                              void* d_out, int out_size) {
    const float* features = (const float*)d_in[0];
    const float* w1 = (const float*)d_in[1];
    const float* b1 = (const float*)d_in[2];
    const float* w2 = (const float*)d_in[3];
    const float* b2 = (const float*)d_in[4];
    const float* w3 = (const float*)d_in[5];
    const float* b3 = (const float*)d_in[6];
    const int* in1 = (const int*)d_in[8];
    float* out = (float*)d_out;

    cudaFuncSetAttribute(fused_kernel,
                         cudaFuncAttributeMaxDynamicSharedMemorySize, SMEM_BYTES);

    const int eblocks = (NEDGE_HALF / 16 + 255) / 256;   // 157
    prep_edges<<<eblocks, 256>>>(in1, w1, 0);            // launch 0
    prep_edges<<<eblocks, 256>>>(in1, w1, NEDGE_HALF);   // launch 1
    prep_feat<<<128 + 79, 256>>>(features, w2, b1, b2, w3, b3);  // launch 2
    fused_kernel<<<GRID, THREADS, SMEM_BYTES>>>();               // launch 3
    transpose_out<<<dim3(NGENES / 32, BATCH / 32), dim3(32, 8)>>>(out);  // launch 4
}

// round 13
// speedup vs baseline: 1.2159x; 1.2159x over previous
#include <cuda_runtime.h>
#include <cuda_fp16.h>

#define BATCH 128
#define NTF 1024
#define NGENES 20000
#define NPAIRS (NGENES / 2)      // 10000 gene-pairs
#define NEDGE1 (NGENES * 64)     // 1,280,000 layer-1 edges
#define NEDGE_HALF (NEDGE1 / 2)
#define CHUNK 64                 // batch elements per block
#define THREADS 1024             // 32 warps
#define GRID 148                 // one wave, 74 blocks per chunk
#define WARPS_PER_CHUNK 2368     // 74 blocks * 32 warps
#define SMEM_BYTES (NTF * CHUNK * 2)  // 131072
#define TAIL_W (NPAIRS - 4 * WARPS_PER_CHUNK)   // 528

// device scratch
__device__ __half g_xTh[NTF * BATCH];        // transposed fp16 features
__device__ unsigned short g_i16[NEDGE1];     // u16 edge indices
__device__ __half g_w1h[NEDGE1];             // fp16 layer-1 weights
__device__ uint4  g_tail[NGENES * 4];        // 64B/gene packed tail
__device__ __half g_yTh[NGENES * BATCH];     // gene-major fp16 output

__device__ __forceinline__ unsigned int packh2(float a, float b) {
    const __half2 h = __float22half2_rn(make_float2(a, b));
    return *reinterpret_cast<const unsigned int*>(&h);
}
__device__ __forceinline__ unsigned int pack16(int a, int b) {
    return (unsigned int)a | ((unsigned int)b << 16);
}

// ---- prep A/B: edge tables, 16 edges/thread, half per launch ----
__global__ void prep_edges(const int* __restrict__ in1,
                           const float* __restrict__ w1, int base) {
    const int e = base + (blockIdx.x * 256 + threadIdx.x) * 16;
    if (e + 16 <= base + NEDGE_HALF) {
        const int4 i0 = __ldg((const int4*)(in1 + e));
        const int4 i1 = __ldg((const int4*)(in1 + e) + 1);
        const int4 i2 = __ldg((const int4*)(in1 + e) + 2);
        const int4 i3 = __ldg((const int4*)(in1 + e) + 3);
        const float4 a0 = __ldg((const float4*)(w1 + e));
        const float4 a1 = __ldg((const float4*)(w1 + e) + 1);
        const float4 a2 = __ldg((const float4*)(w1 + e) + 2);
        const float4 a3 = __ldg((const float4*)(w1 + e) + 3);
        uint4 ia, ib, wa, wb;
        ia.x = pack16(i0.x, i0.y); ia.y = pack16(i0.z, i0.w);
        ia.z = pack16(i1.x, i1.y); ia.w = pack16(i1.z, i1.w);
        ib.x = pack16(i2.x, i2.y); ib.y = pack16(i2.z, i2.w);
        ib.z = pack16(i3.x, i3.y); ib.w = pack16(i3.z, i3.w);
        wa.x = packh2(a0.x, a0.y); wa.y = packh2(a0.z, a0.w);
        wa.z = packh2(a1.x, a1.y); wa.w = packh2(a1.z, a1.w);
        wb.x = packh2(a2.x, a2.y); wb.y = packh2(a2.z, a2.w);
        wb.z = packh2(a3.x, a3.y); wb.w = packh2(a3.z, a3.w);
        *(uint4*)(g_i16 + e) = ia;
        *(uint4*)(g_i16 + e + 8) = ib;
        *(uint4*)(g_w1h + e) = wa;
        *(uint4*)(g_w1h + e + 8) = wb;
    }
}

// ---- prep C: feature transpose + tail structs ----
__global__ void prep_feat(const float* __restrict__ f,
                          const float* __restrict__ w2,
                          const float* __restrict__ b1,
                          const float* __restrict__ b2,
                          const float* __restrict__ w3,
                          const float* __restrict__ b3) {
    const int bid = blockIdx.x;
    if (bid < 128) {
        __shared__ float tile[32][33];
        const int tx = threadIdx.x & 31, ty = threadIdx.x >> 5;
        const int t0 = (bid & 31) * 32;   // TF base
        const int b0 = (bid >> 5) * 32;   // batch base
#pragma unroll
        for (int j = 0; j < 32; j += 8)
            tile[ty + j][tx] = f[(b0 + ty + j) * NTF + t0 + tx];
        __syncthreads();
#pragma unroll
        for (int j = 0; j < 32; j += 8)
            g_xTh[(t0 + ty + j) * BATCH + b0 + tx] = __float2half(tile[tx][ty + j]);
    } else {
        const int g = (bid - 128) * 256 + threadIdx.x;
        if (g < NGENES) {
            const float4 q0 = __ldg((const float4*)(w2 + g * 16));
            const float4 q1 = __ldg((const float4*)(w2 + g * 16) + 1);
            const float4 q2 = __ldg((const float4*)(w2 + g * 16) + 2);
            const float4 q3 = __ldg((const float4*)(w2 + g * 16) + 3);
            const float4 b1q = __ldg((const float4*)(b1 + g * 4));
            const float4 b2q = __ldg((const float4*)(b2 + g * 4));
            const float4 w3q = __ldg((const float4*)(w3 + g * 4));
            const float  b3s = __ldg(b3 + g);
            uint4 u0, u1, u2, u3;
            u0.x = packh2(q0.x, q0.y); u0.y = packh2(q0.z, q0.w);
            u0.z = packh2(q1.x, q1.y); u0.w = packh2(q1.z, q1.w);
            u1.x = packh2(q2.x, q2.y); u1.y = packh2(q2.z, q2.w);
            u1.z = packh2(q3.x, q3.y); u1.w = packh2(q3.z, q3.w);
            u2.x = packh2(b1q.x, b1q.y); u2.y = packh2(b1q.z, b1q.w);
            u2.z = packh2(b2q.x, b2q.y); u2.w = packh2(b2q.z, b2q.w);
            u3.x = packh2(w3q.x, w3q.y); u3.y = packh2(w3q.z, w3q.w);
            u3.z = __float_as_uint(b3s);  u3.w = 0u;
            uint4* dst = g_tail + (size_t)g * 4;
            dst[0] = u0; dst[1] = u1; dst[2] = u2; dst[3] = u3;
        }
    }
}

// g_yTh [NGENES][BATCH] fp16 -> out [BATCH][NGENES] fp32
__global__ void transpose_out(float* __restrict__ out) {
    __shared__ float tile[32][33];
    const int tx = threadIdx.x, ty = threadIdx.y;
    const int g0 = blockIdx.x * 32;
    const int b0 = blockIdx.y * 32;
#pragma unroll
    for (int j = 0; j < 32; j += 8)
        tile[ty + j][tx] = __half2float(g_yTh[(size_t)(g0 + ty + j) * BATCH + b0 + tx]);
    __syncthreads();
#pragma unroll
    for (int j = 0; j < 32; j += 8)
        out[(size_t)(b0 + ty + j) * NGENES + g0 + tx] = tile[tx][ty + j];
}

__device__ __forceinline__ __half2 u2h(unsigned int u) {
    return *reinterpret_cast<__half2*>(&u);
}
__device__ __forceinline__ float tanh_mufu(float x) {
    float y;
    asm("tanh.approx.f32 %0, %1;" : "=f"(y) : "f"(x));
    return y;
}
__device__ __forceinline__ __half2 tanh_h2f(float2 a) {
    __half2 h = __float22half2_rn(a);
    unsigned int u = *reinterpret_cast<unsigned int*>(&h), r;
    asm("tanh.approx.f16x2 %0, %1;" : "=r"(r) : "r"(u));
    return u2h(r);
}

// 4 edges (2 packed index words), LDS.64 row gathers, fp16 chain, fp32 acc
__device__ __forceinline__ void edge_group(const char* fb, unsigned int e01,
                                           unsigned int e23, unsigned int wlo,
                                           unsigned int whi, float4& acc) {
    const uint2 x0 = *(const uint2*)(fb + ((e01 & 0xFFFFu) << 7));
    const uint2 x1 = *(const uint2*)(fb + ((e01 >> 16) << 7));
    const uint2 x2 = *(const uint2*)(fb + ((e23 & 0xFFFFu) << 7));
    const uint2 x3 = *(const uint2*)(fb + ((e23 >> 16) << 7));
    __half2 alo = __hmul2(__low2half2(u2h(wlo)),  u2h(x0.x));
    __half2 ahi = __hmul2(__low2half2(u2h(wlo)),  u2h(x0.y));
    alo = __hfma2(__high2half2(u2h(wlo)), u2h(x1.x), alo);
    ahi = __hfma2(__high2half2(u2h(wlo)), u2h(x1.y), ahi);
    alo = __hfma2(__low2half2(u2h(whi)),  u2h(x2.x), alo);
    ahi = __hfma2(__low2half2(u2h(whi)),  u2h(x2.y), ahi);
    alo = __hfma2(__high2half2(u2h(whi)), u2h(x3.x), alo);
    ahi = __hfma2(__high2half2(u2h(whi)), u2h(x3.y), ahi);
    const float2 flo = __half22float2(alo);
    const float2 fhi = __half22float2(ahi);
    acc.x += flo.x; acc.y += flo.y; acc.z += fhi.x; acc.w += fhi.y;
}

// layer-1 node: 16 edges, metadata loaded in two halves (low reg pressure),
// bias folded at the final reduction
__device__ __forceinline__ void l1_node(const char* fb, const uint4* ip,
                                        const uint4* wp, int n, float bias,
                                        __half2& hlo, __half2& hhi) {
    const uint4 ia = __ldg(ip + 2 * n);
    const uint4 wa = __ldg(wp + 2 * n);
    float4 a0 = make_float4(0.f, 0.f, 0.f, 0.f);
    float4 a1 = make_float4(0.f, 0.f, 0.f, 0.f);
    edge_group(fb, ia.x, ia.y, wa.x, wa.y, a0);
    edge_group(fb, ia.z, ia.w, wa.z, wa.w, a1);
    const uint4 ib = __ldg(ip + 2 * n + 1);
    const uint4 wb = __ldg(wp + 2 * n + 1);
    edge_group(fb, ib.x, ib.y, wb.x, wb.y, a0);
    edge_group(fb, ib.z, ib.w, wb.z, wb.w, a1);
    hlo = tanh_h2f(make_float2(a0.x + a1.x + bias, a0.y + a1.y + bias));
    hhi = tanh_h2f(make_float2(a0.z + a1.z + bias, a0.w + a1.w + bias));
}

// layer-2 node (fp16 MAC) + fp32 tanh + fp32 layer-3 accumulate
__device__ __forceinline__ void l23_node(const __half2* h1lo, const __half2* h1hi,
                                         unsigned int wlo, unsigned int whi,
                                         float b2o, float w3o, float4& y) {
    const __half2 bb = __half2half2(__float2half(b2o));
    __half2 slo = bb, shi = bb;
    slo = __hfma2(__low2half2(u2h(wlo)),  h1lo[0], slo);
    shi = __hfma2(__low2half2(u2h(wlo)),  h1hi[0], shi);
    slo = __hfma2(__high2half2(u2h(wlo)), h1lo[1], slo);
    shi = __hfma2(__high2half2(u2h(wlo)), h1hi[1], shi);
    slo = __hfma2(__low2half2(u2h(whi)),  h1lo[2], slo);
    shi = __hfma2(__low2half2(u2h(whi)),  h1hi[2], shi);
    slo = __hfma2(__high2half2(u2h(whi)), h1lo[3], slo);
    shi = __hfma2(__high2half2(u2h(whi)), h1hi[3], shi);
    const float2 a = __half22float2(slo);
    const float2 b = __half22float2(shi);
    y.x = fmaf(w3o, tanh_mufu(a.x), y.x);
    y.y = fmaf(w3o, tanh_mufu(a.y), y.y);
    y.z = fmaf(w3o, tanh_mufu(b.x), y.z);
    y.w = fmaf(w3o, tanh_mufu(b.y), y.w);
}

// layers 2+3 for one gene + fp16 store
__device__ __forceinline__ void l23_store(const __half2* h1lo, const __half2* h1hi,
                                          uint4 u0, uint4 u1, uint4 u2, uint4 u3,
                                          int g, int b0, int bsub) {
    const float2 b2a = __half22float2(u2h(u2.z));
    const float2 b2b = __half22float2(u2h(u2.w));
    const float2 w3a = __half22float2(u2h(u3.x));
    const float2 w3b = __half22float2(u2h(u3.y));
    const float  yb  = __uint_as_float(u3.z);
    float4 y = make_float4(yb, yb, yb, yb);
    l23_node(h1lo, h1hi, u0.x, u0.y, b2a.x, w3a.x, y);
    l23_node(h1lo, h1hi, u0.z, u0.w, b2a.y, w3a.y, y);
    l23_node(h1lo, h1hi, u1.x, u1.y, b2b.x, w3b.x, y);
    l23_node(h1lo, h1hi, u1.z, u1.w, b2b.y, w3b.y, y);
    const __half2 ylo = __float22half2_rn(make_float2(y.x, y.y));
    const __half2 yhi = __float22half2_rn(make_float2(y.z, y.w));
    uint2 yy;
    yy.x = *reinterpret_cast<const unsigned int*>(&ylo);
    yy.y = *reinterpret_cast<const unsigned int*>(&yhi);
    *(uint2*)&g_yTh[(size_t)g * BATCH + b0 + bsub * 4] = yy;
}

// single-gene compute (tail path)
__device__ __forceinline__ void compute_one(const char* fb, int g, int b0, int bsub) {
    const uint4* ip = (const uint4*)(g_i16 + (size_t)g * 64);
    const uint4* wp = (const uint4*)(g_w1h + (size_t)g * 64);
    const uint4* tp = g_tail + (size_t)g * 4;
    const uint4 u2 = __ldg(tp + 2);
    const uint4 u3 = __ldg(tp + 3);
    const float2 b1a = __half22float2(u2h(u2.x));
    const float2 b1b = __half22float2(u2h(u2.y));
    __half2 h1lo[4], h1hi[4];
    l1_node(fb, ip, wp, 0, b1a.x, h1lo[0], h1hi[0]);
    l1_node(fb, ip, wp, 1, b1a.y, h1lo[1], h1hi[1]);
    const uint4 u0 = __ldg(tp + 0);
    const uint4 u1 = __ldg(tp + 1);
    l1_node(fb, ip, wp, 2, b1b.x, h1lo[2], h1hi[2]);
    l1_node(fb, ip, wp, 3, b1b.y, h1lo[3], h1hi[3]);
    l23_store(h1lo, h1hi, u0, u1, u2, u3, g, b0, bsub);
}

__global__ void __launch_bounds__(THREADS, 1) fused_kernel() {
    extern __shared__ unsigned int xs[];   // [NTF][32] uint -> 128B fp16 rows
    const int tid = threadIdx.x;
    const int chunk = blockIdx.x & 1;      // 148 blocks -> 74 per chunk
    const int b0 = chunk * CHUNK;

    // fill feature slice (rows of 64 fp16 = 8 uint4)
    {
        const uint4* src = (const uint4*)g_xTh;  // global row = 16 uint4
        uint4* dst = (uint4*)xs;
#pragma unroll
        for (int i = tid; i < NTF * 8; i += THREADS) {
            const int t = i >> 3, c = i & 7;
            dst[i] = src[t * 16 + chunk * 8 + c];
        }
    }
    __syncthreads();

    const int lane = tid & 31;
    const int gl   = lane >> 4;     // gene within pair (0..1)
    const int bsub = lane & 15;     // batch quad -> batches b0+bsub*4 .. +3
    const char* fb = (const char*)xs + bsub * 8;   // lane's 4-batch column
    const int w = (blockIdx.x >> 1) * 32 + (tid >> 5);  // 0..2367 in chunk

    // two dual-gene iterations: A and B are independent chains -> 2x ILP
#pragma unroll 1
    for (int k = 0; k < 2; k++) {
        const int gA = ((2 * k) * WARPS_PER_CHUNK + w) * 2 + gl;
        const int gB = ((2 * k + 1) * WARPS_PER_CHUNK + w) * 2 + gl;
        const uint4* ipA = (const uint4*)(g_i16 + (size_t)gA * 64);
        const uint4* wpA = (const uint4*)(g_w1h + (size_t)gA * 64);
        const uint4* tpA = g_tail + (size_t)gA * 4;
        const uint4* ipB = (const uint4*)(g_i16 + (size_t)gB * 64);
        const uint4* wpB = (const uint4*)(g_w1h + (size_t)gB * 64);
        const uint4* tpB = g_tail + (size_t)gB * 4;

        const uint4 u2A = __ldg(tpA + 2), u3A = __ldg(tpA + 3);
        const uint4 u2B = __ldg(tpB + 2), u3B = __ldg(tpB + 3);
        const float2 b1aA = __half22float2(u2h(u2A.x));
        const float2 b1bA = __half22float2(u2h(u2A.y));
        const float2 b1aB = __half22float2(u2h(u2B.x));
        const float2 b1bB = __half22float2(u2h(u2B.y));

        __half2 hAlo[4], hAhi[4], hBlo[4], hBhi[4];
        l1_node(fb, ipA, wpA, 0, b1aA.x, hAlo[0], hAhi[0]);
        l1_node(fb, ipB, wpB, 0, b1aB.x, hBlo[0], hBhi[0]);
        l1_node(fb, ipA, wpA, 1, b1aA.y, hAlo[1], hAhi[1]);
        l1_node(fb, ipB, wpB, 1, b1aB.y, hBlo[1], hBhi[1]);
        l1_node(fb, ipA, wpA, 2, b1bA.x, hAlo[2], hAhi[2]);
        l1_node(fb, ipB, wpB, 2, b1bB.x, hBlo[2], hBhi[2]);
        const uint4 u0A = __ldg(tpA + 0), u1A = __ldg(tpA + 1);
        l1_node(fb, ipA, wpA, 3, b1bA.y, hAlo[3], hAhi[3]);
        const uint4 u0B = __ldg(tpB + 0), u1B = __ldg(tpB + 1);
        l1_node(fb, ipB, wpB, 3, b1bB.y, hBlo[3], hBhi[3]);

        l23_store(hAlo, hAhi, u0A, u1A, u2A, u3A, gA, b0, bsub);
        l23_store(hBlo, hBhi, u0B, u1B, u2B, u3B, gB, b0, bsub);
    }

    // tail: 528 warps per chunk process one extra pair
    if (w < TAIL_W) {
        const int g = (4 * WARPS_PER_CHUNK + w) * 2 + gl;
        compute_one(fb, g, b0, bsub);
    }
}

extern "C" void kernel_launch(void* const* d_in, const int* in_sizes, int n_in,
                              void* d_out, int out_size) {
    const float* features = (const float*)d_in[0];
    const float* w1 = (const float*)d_in[1];
    const float* b1 = (const float*)d_in[2];
    const float* w2 = (const float*)d_in[3];
    const float* b2 = (const float*)d_in[4];
    const float* w3 = (const float*)d_in[5];
    const float* b3 = (const float*)d_in[6];
    const int* in1 = (const int*)d_in[8];
    float* out = (float*)d_out;

    cudaFuncSetAttribute(fused_kernel,
                         cudaFuncAttributeMaxDynamicSharedMemorySize, SMEM_BYTES);

    const int eblocks = (NEDGE_HALF / 16 + 255) / 256;   // 157
    prep_edges<<<eblocks, 256>>>(in1, w1, 0);            // launch 0
    prep_edges<<<eblocks, 256>>>(in1, w1, NEDGE_HALF);   // launch 1
    prep_feat<<<128 + 79, 256>>>(features, w2, b1, b2, w3, b3);  // launch 2
    fused_kernel<<<GRID, THREADS, SMEM_BYTES>>>();               // launch 3 (ncu target)
    transpose_out<<<dim3(NGENES / 32, BATCH / 32), dim3(32, 8)>>>(out);  // launch 4
}